// round 16
// baseline (speedup 1.0000x reference)
#include <cuda_runtime.h>
#include <cuda_fp16.h>
#include <cstdint>
#include <math.h>

#define N_ROWS 4096
#define DIM    1024
#define TMB    128
#define TNB    128
#define KSTEP  64                  // fp16 elems per chunk = 128B per row
#define NCHUNK (DIM / KSTEP)       // 16
#define NCT    (N_ROWS / TNB)      // 32
#define NTILES (NCT * (N_ROWS / TMB))   // 1024
#define GRIDP  304                 // persistent CTAs (2 per SM)
#define THR    0.010f
#define NSTAGE 3

#define CHUNK_BYTES 16384          // 128 rows x 128 B, per operand
#define STAGE_BYTES 32768          // A chunk + B chunk
#define EPI_BYTES   8192
#define SMEM_BYTES  (NSTAGE * STAGE_BYTES + EPI_BYTES + 1024)

// ---------------- device scratch ----------------
__device__ __half g_At[N_ROWS * DIM];   // tiled + pre-swizzled
__device__ __half g_Bt[N_ROWS * DIM];
__device__ float g_v1[N_ROWS * NCT];
__device__ int   g_i1[N_ROWS * NCT];
__device__ float g_v2[N_ROWS * NCT];
__device__ int   g_i2[N_ROWS * NCT];
__device__ int   g_count;
__device__ int   g_done;

// ---------------- helpers ----------------
__device__ __forceinline__ uint32_t smem_u32(const void* p) {
    uint32_t a;
    asm("{ .reg .u64 t; cvta.to.shared.u64 t, %1; cvt.u32.u64 %0, t; }" : "=r"(a) : "l"(p));
    return a;
}
#define SWZ(bo) ((bo) ^ (((bo) >> 3) & 0x70))

#define MBARRIER_INIT(mbar, cnt) \
    asm volatile("mbarrier.init.shared.b64 [%0], %1;" :: "r"((uint32_t)(mbar)), "r"((uint32_t)(cnt)) : "memory")
#define MBARRIER_EXPECT_TX(mbar, bytes) \
    asm volatile("mbarrier.arrive.expect_tx.shared.b64 _, [%0], %1;" \
                 :: "r"((uint32_t)(mbar)), "r"((uint32_t)(bytes)) : "memory")
#define MBARRIER_ARRIVE(mbar) \
    asm volatile("mbarrier.arrive.shared.b64 _, [%0];" :: "r"((uint32_t)(mbar)) : "memory")

#define MBARRIER_WAIT_PARITY(mbar_smem_addr, phase_parity) do {                                  \
    uint32_t _mbar = (uint32_t)(mbar_smem_addr);                                                 \
    uint32_t _parity = (uint32_t)(phase_parity);                                                 \
    uint32_t _done;                                                                              \
    asm volatile(                                                                                \
        "{\n\t.reg .pred p;\n\t"                                                                 \
        "mbarrier.try_wait.parity.acquire.cta.shared::cta.b64 p, [%1], %2;\n\t"                  \
        "selp.b32 %0, 1, 0, p;\n\t}"                                                             \
        : "=r"(_done) : "r"(_mbar), "r"(_parity) : "memory");                                    \
    if (!_done) {                                                                                \
        asm volatile(                                                                            \
            "{\n\t.reg .pred P1;\n\t"                                                            \
            "WAIT_LOOP_%=:\n\t"                                                                  \
            "mbarrier.try_wait.parity.acquire.cta.shared::cta.b64 P1, [%0], %1, 0x989680;\n\t"   \
            "@P1 bra.uni WAIT_DONE_%=;\n\t"                                                      \
            "bra.uni WAIT_LOOP_%=;\n\t"                                                          \
            "WAIT_DONE_%=:\n\t}"                                                                 \
            :: "r"(_mbar), "r"(_parity) : "memory");                                             \
    }                                                                                            \
} while (0)

__device__ __forceinline__ void bulk_g2s(uint32_t dst, const void* gsrc, uint32_t bytes,
                                         uint32_t mbar) {
    asm volatile(
        "cp.async.bulk.shared::cluster.global.mbarrier::complete_tx::bytes [%0], [%1], %2, [%3];"
        :: "r"(dst), "l"(gsrc), "r"(bytes), "r"(mbar) : "memory");
}
__device__ __forceinline__ void ldsm_x4(uint32_t addr, uint32_t& r0, uint32_t& r1,
                                        uint32_t& r2, uint32_t& r3) {
    asm volatile("ldmatrix.sync.aligned.m8n8.x4.shared.b16 {%0,%1,%2,%3}, [%4];"
                 : "=r"(r0), "=r"(r1), "=r"(r2), "=r"(r3) : "r"(addr));
}
__device__ __forceinline__ void mma_f16(float* d, const uint32_t* a, const uint32_t* b) {
    asm volatile(
        "mma.sync.aligned.m16n8k16.row.col.f32.f16.f16.f32 "
        "{%0,%1,%2,%3}, {%4,%5,%6,%7}, {%8,%9}, {%0,%1,%2,%3};"
        : "+f"(d[0]), "+f"(d[1]), "+f"(d[2]), "+f"(d[3])
        : "r"(a[0]), "r"(a[1]), "r"(a[2]), "r"(a[3]), "r"(b[0]), "r"(b[1]));
}
__device__ __forceinline__ uint32_t pk2h(float a, float b) {
    __half2 t = __floats2half2_rn(a, b);
    return *reinterpret_cast<uint32_t*>(&t);
}

// ---------------------------------------------------------------------------
// K0: build tiled+swizzled fp16 A (pos) and B (normalized anchors).
// 2048 blocks x 256 threads: 2 rows per block (R12 layout per row).
// ---------------------------------------------------------------------------
__global__ __launch_bounds__(256) void prep_kernel(const float* __restrict__ x) {
    const int t  = threadIdx.x;
    const int rs = t >> 7;            // row select 0/1
    const int tt = t & 127;
    const int j  = blockIdx.x * 2 + rs;
    const int by = j >> 7;
    const int r  = j & 127;
    const int c  = tt >> 3;           // chunk 0..15
    const int kc = (tt & 7) * 8;      // col within chunk

    const float4* px = reinterpret_cast<const float4*>(x + (size_t)j * 2048 + tt * 8);
    const float4 p0 = px[0], p1 = px[1];
    const float4* ax = reinterpret_cast<const float4*>(x + (size_t)j * 2048 + 1024 + tt * 8);
    const float4 a0 = ax[0], a1 = ax[1];

    float ss = a0.x * a0.x + a0.y * a0.y + a0.z * a0.z + a0.w * a0.w
             + a1.x * a1.x + a1.y * a1.y + a1.z * a1.z + a1.w * a1.w;
    __shared__ float wsum[2][4];
    __shared__ float s_rinv[2];
    #pragma unroll
    for (int o = 16; o > 0; o >>= 1) ss += __shfl_xor_sync(0xffffffffu, ss, o);
    if ((tt & 31) == 0) wsum[rs][tt >> 5] = ss;
    __syncthreads();
    if (tt == 0) {
        const float tot = wsum[rs][0] + wsum[rs][1] + wsum[rs][2] + wsum[rs][3];
        s_rinv[rs] = 1.0f / sqrtf(fmaxf(tot, 1e-30f));
        if (j == 0) { g_count = 0; g_done = 0; }
    }
    __syncthreads();
    const float rinv = s_rinv[rs];

    const uint32_t off = SWZ((uint32_t)(r * 128 + kc * 2));
    const size_t tileA = ((size_t)by * NCHUNK + c) * CHUNK_BYTES;

    uint4 v;
    v.x = pk2h(p0.x, p0.y); v.y = pk2h(p0.z, p0.w);
    v.z = pk2h(p1.x, p1.y); v.w = pk2h(p1.z, p1.w);
    *reinterpret_cast<uint4*>(reinterpret_cast<char*>(g_At) + tileA + off) = v;

    v.x = pk2h(a0.x * rinv, a0.y * rinv); v.y = pk2h(a0.z * rinv, a0.w * rinv);
    v.z = pk2h(a1.x * rinv, a1.y * rinv); v.w = pk2h(a1.z * rinv, a1.w * rinv);
    *reinterpret_cast<uint4*>(reinterpret_cast<char*>(g_Bt) + tileA + off) = v;
}

// ---------------------------------------------------------------------------
// K1: persistent fp16 GEMM with warp-skew-tolerant full/empty mbarrier
// pipeline (NO per-chunk __syncthreads). Static tiles, continuous 3-buffer
// cp.async.bulk stream, fused per-tile top-2 epilogue.
//
// Protocol (buffer s, u-th use = chunk g, u = g/NSTAGE):
//   producer(tid0): wait empty[s] parity (u&1)^1  -> expect_tx + 2x bulk
//   consumer(all):  wait full[s] parity (u&1)     -> compute
//   each warp lane0 arrives empty[s] (count 8) after compute.
// First use: empty wait parity 1 passes on a fresh barrier.
// ---------------------------------------------------------------------------
__global__ __launch_bounds__(256) void gemm_kernel() {
    extern __shared__ char dyn_smem[];
    char* sm = (char*)((((uintptr_t)dyn_smem) + 1023) & ~(uintptr_t)1023);
    const uint32_t sbase = smem_u32(sm);
    char* epi = sm + NSTAGE * STAGE_BYTES;

    __shared__ __align__(8) uint64_t s_mbF[NSTAGE];
    __shared__ __align__(8) uint64_t s_mbE[NSTAGE];

    const int tid = threadIdx.x;
    const int wid = tid >> 5;
    const int lid = tid & 31;
    const int wm = (wid >> 2) * 64;
    const int wn = (wid & 3) * 32;

    uint32_t mbF[NSTAGE], mbE[NSTAGE];
    #pragma unroll
    for (int s = 0; s < NSTAGE; s++) {
        mbF[s] = smem_u32(&s_mbF[s]);
        mbE[s] = smem_u32(&s_mbE[s]);
    }
    if (tid == 0) {
        #pragma unroll
        for (int s = 0; s < NSTAGE; s++) {
            MBARRIER_INIT(mbF[s], 1);
            MBARRIER_INIT(mbE[s], 8);    // one arrive per warp
        }
    }
    asm volatile("fence.proxy.async.shared::cta;" ::: "memory");
    __syncthreads();

    const int bid = blockIdx.x;
    int ntiles = 0;
    for (int t = bid; t < NTILES; t += GRIDP) ntiles++;
    if (ntiles == 0) return;
    const int nchunks = ntiles * NCHUNK;

    auto issue_load = [&](int gidx) {
        // tid==0 only
        const int buf = gidx % NSTAGE;
        const int u = gidx / NSTAGE;
        MBARRIER_WAIT_PARITY(mbE[buf], (u & 1) ^ 1);   // backpressure
        const int tile = bid + (gidx >> 4) * GRIDP;
        const int c = gidx & (NCHUNK - 1);
        const int by = tile >> 5;
        const int bx = tile & 31;
        MBARRIER_EXPECT_TX(mbF[buf], STAGE_BYTES);
        bulk_g2s(sbase + buf * STAGE_BYTES,
                 reinterpret_cast<const char*>(g_At) + ((size_t)by * NCHUNK + c) * CHUNK_BYTES,
                 CHUNK_BYTES, mbF[buf]);
        bulk_g2s(sbase + buf * STAGE_BYTES + CHUNK_BYTES,
                 reinterpret_cast<const char*>(g_Bt) + ((size_t)bx * NCHUNK + c) * CHUNK_BYTES,
                 CHUNK_BYTES, mbF[buf]);
    };

    const int a_row = lid & 15;
    const int a_u   = lid >> 4;
    const int b_row = (lid & 7) + ((lid >> 4) << 3);
    const int b_u   = (lid >> 3) & 1;
    const int quad  = lid & 3;

    float acc[4][4][4];

    auto compute_stage = [&](int buf) {
        const uint32_t stA = sbase + buf * STAGE_BYTES;
        const uint32_t stB = stA + CHUNK_BYTES;
        #pragma unroll
        for (int kk = 0; kk < 4; kk++) {
            uint32_t ah[4][4], bh[4][2];
            #pragma unroll
            for (int mf = 0; mf < 4; mf++) {
                const uint32_t bo = (uint32_t)((wm + mf * 16 + a_row) * 128 + kk * 32 + a_u * 16);
                ldsm_x4(stA + SWZ(bo), ah[mf][0], ah[mf][1], ah[mf][2], ah[mf][3]);
            }
            #pragma unroll
            for (int nf2 = 0; nf2 < 2; nf2++) {
                const uint32_t bo = (uint32_t)((wn + nf2 * 16 + b_row) * 128 + kk * 32 + b_u * 16);
                uint32_t r0, r1, r2, r3;
                ldsm_x4(stB + SWZ(bo), r0, r1, r2, r3);
                bh[nf2 * 2][0] = r0;     bh[nf2 * 2][1] = r1;
                bh[nf2 * 2 + 1][0] = r2; bh[nf2 * 2 + 1][1] = r3;
            }
            #pragma unroll
            for (int mf = 0; mf < 4; mf++)
                #pragma unroll
                for (int nf = 0; nf < 4; nf++)
                    mma_f16(acc[mf][nf], ah[mf], bh[nf]);
        }
    };

    if (tid == 0) { issue_load(0); issue_load(1); }

    #pragma unroll 1
    for (int g = 0; g < nchunks; ++g) {
        const int c = g & (NCHUNK - 1);
        const int buf = g % NSTAGE;
        if (c == 0) {
            #pragma unroll
            for (int m = 0; m < 4; m++)
                #pragma unroll
                for (int n = 0; n < 4; n++)
                    #pragma unroll
                    for (int e = 0; e < 4; e++) acc[m][n][e] = 0.f;
        }
        MBARRIER_WAIT_PARITY(mbF[buf], (g / NSTAGE) & 1);
        if (tid == 0 && g + 2 < nchunks) issue_load(g + 2);
        compute_stage(buf);
        if (lid == 0) MBARRIER_ARRIVE(mbE[buf]);   // this warp done with buf

        if (c == NCHUNK - 1) {
            // ---------- epilogue for this tile (loads continue in flight) ----------
            const int tile = bid + (g >> 4) * GRIDP;
            const int by = tile >> 5;
            const int bx = tile & 31;
            const int i0 = by * TMB;
            const int j0 = bx * TNB;

            float* rV1 = (float*)epi;                   // [128][4]
            int*   rI1 = (int*)(epi + 2048);
            float* rV2 = (float*)(epi + 4096);
            int*   rI2 = (int*)(epi + 6144);

            #pragma unroll
            for (int mf = 0; mf < 4; mf++) {
                #pragma unroll
                for (int half = 0; half < 2; half++) {
                    float v1 = -INFINITY, v2 = -INFINITY;
                    int i1 = 0, i2 = 0;
                    #pragma unroll
                    for (int nf = 0; nf < 4; nf++) {
                        #pragma unroll
                        for (int i = 0; i < 2; i++) {
                            const float v = acc[mf][nf][half * 2 + i];
                            const int cc = nf * 8 + quad * 2 + i;
                            if (v > v1) { v2 = v1; i2 = i1; v1 = v; i1 = cc; }
                            else if (v > v2) { v2 = v; i2 = cc; }
                        }
                    }
                    #pragma unroll
                    for (int o = 1; o <= 2; o <<= 1) {
                        const float ov1 = __shfl_xor_sync(0xffffffffu, v1, o);
                        const int   oi1 = __shfl_xor_sync(0xffffffffu, i1, o);
                        const float ov2 = __shfl_xor_sync(0xffffffffu, v2, o);
                        const int   oi2 = __shfl_xor_sync(0xffffffffu, i2, o);
                        if (ov1 > v1 || (ov1 == v1 && oi1 < i1)) {
                            if (v1 > ov2 || (v1 == ov2 && i1 < oi2)) { v2 = v1; i2 = i1; }
                            else { v2 = ov2; i2 = oi2; }
                            v1 = ov1; i1 = oi1;
                        } else {
                            if (ov1 > v2) { v2 = ov1; i2 = oi1; }
                        }
                    }
                    if (quad == 0) {
                        const int row = wm + mf * 16 + (lid >> 2) + half * 8;
                        const int w = wid & 3;
                        rV1[row * 4 + w] = v1; rI1[row * 4 + w] = wn + i1;
                        rV2[row * 4 + w] = v2; rI2[row * 4 + w] = wn + i2;
                    }
                }
            }
            __syncthreads();
            if (tid < 128) {
                float V1 = rV1[tid * 4], V2 = rV2[tid * 4];
                int I1 = rI1[tid * 4], I2 = rI2[tid * 4];
                #pragma unroll
                for (int w = 1; w < 4; w++) {
                    const float v1 = rV1[tid * 4 + w], v2 = rV2[tid * 4 + w];
                    const int i1 = rI1[tid * 4 + w], i2 = rI2[tid * 4 + w];
                    if (v1 > V1) {
                        if (V1 >= v2) { V2 = V1; I2 = I1; } else { V2 = v2; I2 = i2; }
                        V1 = v1; I1 = i1;
                    } else if (v1 > V2) { V2 = v1; I2 = i1; }
                }
                const size_t o = (size_t)(i0 + tid) * NCT + bx;
                g_v1[o] = V1; g_i1[o] = j0 + I1;
                g_v2[o] = V2; g_i2[o] = j0 + I2;
            }
            __syncthreads();   // epi buffer reusable next tile
        }
    }
}

// ---------------------------------------------------------------------------
// K2: warp-per-row merge + exact fp32 rescore + final output (R12-proven).
// ---------------------------------------------------------------------------
__global__ __launch_bounds__(256) void rescore_kernel(const float* __restrict__ x,
                                                      float* __restrict__ out) {
    const int tid = threadIdx.x;
    const int lid = tid & 31;
    const int row = blockIdx.x * 8 + (tid >> 5);

    {
        const size_t o = (size_t)row * NCT + lid;
        float v1 = g_v1[o], v2 = g_v2[o];
        int i1 = g_i1[o], i2 = g_i2[o];
        const float mv1 = v1, mv2 = v2;        // per-tile values for filter
        const int mi1 = i1, mi2 = i2;
        #pragma unroll
        for (int off = 1; off <= 16; off <<= 1) {
            const float ov1 = __shfl_xor_sync(0xffffffffu, v1, off);
            const int   oi1 = __shfl_xor_sync(0xffffffffu, i1, off);
            const float ov2 = __shfl_xor_sync(0xffffffffu, v2, off);
            const int   oi2 = __shfl_xor_sync(0xffffffffu, i2, off);
            if (ov1 > v1 || (ov1 == v1 && oi1 < i1)) {
                if (v1 > ov2 || (v1 == ov2 && i1 < oi2)) { v2 = v1; i2 = i1; }
                else { v2 = ov2; i2 = oi2; }
                v1 = ov1; i1 = oi1;
            } else {
                if (ov1 > v2) { v2 = ov1; i2 = oi1; }
            }
        }
        if ((v1 - v2) >= THR) {
            if (lid == 0 && i1 == row) atomicAdd(&g_count, 1);
        } else {
            // ambiguous: exact fp32 rescore of screen candidates (>= V1 - THR)
            const float cut = v1 - THR;
            unsigned m1 = __ballot_sync(0xffffffffu, mv1 >= cut);
            unsigned m2 = __ballot_sync(0xffffffffu, mv2 >= cut);

            const float4* a4 = reinterpret_cast<const float4*>(x + (size_t)row * 2048 + lid * 32);
            float4 ac[8];
            #pragma unroll
            for (int i = 0; i < 8; i++) ac[i] = a4[i];

            float best = -INFINITY;
            int bi = 1 << 30;
            for (int pass = 0; pass < 2; pass++) {
                unsigned m = pass ? m2 : m1;
                while (m) {
                    const int s = __ffs(m) - 1;
                    m &= m - 1;
                    const int cand = __shfl_sync(0xffffffffu, pass ? mi2 : mi1, s);
                    const float4* b4 = reinterpret_cast<const float4*>(x + (size_t)cand * 2048 + 1024 + lid * 32);
                    float dot = 0.f, nrm = 0.f;
                    #pragma unroll
                    for (int i = 0; i < 8; i++) {
                        const float4 a = ac[i];
                        const float4 b = b4[i];
                        dot = fmaf(a.x, b.x, dot); dot = fmaf(a.y, b.y, dot);
                        dot = fmaf(a.z, b.z, dot); dot = fmaf(a.w, b.w, dot);
                        nrm = fmaf(b.x, b.x, nrm); nrm = fmaf(b.y, b.y, nrm);
                        nrm = fmaf(b.z, b.z, nrm); nrm = fmaf(b.w, b.w, nrm);
                    }
                    #pragma unroll
                    for (int of = 16; of > 0; of >>= 1) {
                        dot += __shfl_xor_sync(0xffffffffu, dot, of);
                        nrm += __shfl_xor_sync(0xffffffffu, nrm, of);
                    }
                    const float val = dot / sqrtf(fmaxf(nrm, 1e-30f));
                    if (val > best || (val == best && cand < bi)) { best = val; bi = cand; }
                }
            }
            if (lid == 0 && bi == row) atomicAdd(&g_count, 1);
        }
    }

    // completion: last block writes the outputs
    __syncthreads();
    if (tid == 0) {
        __threadfence();
        if (atomicAdd(&g_done, 1) == gridDim.x - 1) {
            out[0] = 1.0f;   // nloss == exp(0) exactly
            out[1] = ((float)atomicAdd(&g_count, 0) / 4096.0f) * 100.0f;
        }
    }
}

extern "C" void kernel_launch(void* const* d_in, const int* in_sizes, int n_in,
                              void* d_out, int out_size) {
    const float* x = (const float*)d_in[0];
    float* out = (float*)d_out;

    cudaFuncSetAttribute(gemm_kernel, cudaFuncAttributeMaxDynamicSharedMemorySize, SMEM_BYTES);

    prep_kernel<<<N_ROWS / 2, 256>>>(x);
    gemm_kernel<<<GRIDP, 256, SMEM_BYTES>>>();
    rescore_kernel<<<N_ROWS / 8, 256>>>(x, out);
}

// round 17
// speedup vs baseline: 1.0587x; 1.0587x over previous
#include <cuda_runtime.h>
#include <cuda_fp16.h>
#include <cstdint>
#include <math.h>

#define N_ROWS 4096
#define DIM    1024
#define TMB    128
#define TNB    128
#define KSTEP  64                  // fp16 elems per chunk = 128B per row
#define NCHUNK (DIM / KSTEP)       // 16
#define NCT    (N_ROWS / TNB)      // 32
#define NTILES (NCT * (N_ROWS / TMB))   // 1024
#define GRIDP  304                 // persistent CTAs (2 per SM)
#define THR    0.010f
#define NSTAGE 3

#define CHUNK_BYTES 16384          // 128 rows x 128 B, per operand
#define STAGE_BYTES 32768          // A chunk + B chunk
#define EPI_BYTES   8192
#define SMEM_BYTES  (NSTAGE * STAGE_BYTES + EPI_BYTES + 1024)

// ---------------- device scratch ----------------
__device__ __half g_At[N_ROWS * DIM];   // tiled + pre-swizzled
__device__ __half g_Bt[N_ROWS * DIM];
__device__ float g_v1[N_ROWS * NCT];
__device__ int   g_i1[N_ROWS * NCT];
__device__ float g_v2[N_ROWS * NCT];
__device__ int   g_i2[N_ROWS * NCT];
__device__ int   g_count;
__device__ int   g_done;

// ---------------- helpers ----------------
__device__ __forceinline__ uint32_t smem_u32(const void* p) {
    uint32_t a;
    asm("{ .reg .u64 t; cvta.to.shared.u64 t, %1; cvt.u32.u64 %0, t; }" : "=r"(a) : "l"(p));
    return a;
}
#define SWZ(bo) ((bo) ^ (((bo) >> 3) & 0x70))

#define MBARRIER_INIT(mbar, cnt) \
    asm volatile("mbarrier.init.shared.b64 [%0], %1;" :: "r"((uint32_t)(mbar)), "r"((uint32_t)(cnt)) : "memory")
#define MBARRIER_EXPECT_TX(mbar, bytes) \
    asm volatile("mbarrier.arrive.expect_tx.shared.b64 _, [%0], %1;" \
                 :: "r"((uint32_t)(mbar)), "r"((uint32_t)(bytes)) : "memory")

#define MBARRIER_WAIT_PARITY(mbar_smem_addr, phase_parity) do {                                  \
    uint32_t _mbar = (uint32_t)(mbar_smem_addr);                                                 \
    uint32_t _parity = (uint32_t)(phase_parity);                                                 \
    uint32_t _done;                                                                              \
    asm volatile(                                                                                \
        "{\n\t.reg .pred p;\n\t"                                                                 \
        "mbarrier.try_wait.parity.acquire.cta.shared::cta.b64 p, [%1], %2;\n\t"                  \
        "selp.b32 %0, 1, 0, p;\n\t}"                                                             \
        : "=r"(_done) : "r"(_mbar), "r"(_parity) : "memory");                                    \
    if (!_done) {                                                                                \
        asm volatile(                                                                            \
            "{\n\t.reg .pred P1;\n\t"                                                            \
            "WAIT_LOOP_%=:\n\t"                                                                  \
            "mbarrier.try_wait.parity.acquire.cta.shared::cta.b64 P1, [%0], %1, 0x989680;\n\t"   \
            "@P1 bra.uni WAIT_DONE_%=;\n\t"                                                      \
            "bra.uni WAIT_LOOP_%=;\n\t"                                                          \
            "WAIT_DONE_%=:\n\t}"                                                                 \
            :: "r"(_mbar), "r"(_parity) : "memory");                                             \
    }                                                                                            \
} while (0)

__device__ __forceinline__ void bulk_g2s(uint32_t dst, const void* gsrc, uint32_t bytes,
                                         uint32_t mbar) {
    asm volatile(
        "cp.async.bulk.shared::cluster.global.mbarrier::complete_tx::bytes [%0], [%1], %2, [%3];"
        :: "r"(dst), "l"(gsrc), "r"(bytes), "r"(mbar) : "memory");
}
__device__ __forceinline__ void ldsm_x4(uint32_t addr, uint32_t& r0, uint32_t& r1,
                                        uint32_t& r2, uint32_t& r3) {
    asm volatile("ldmatrix.sync.aligned.m8n8.x4.shared.b16 {%0,%1,%2,%3}, [%4];"
                 : "=r"(r0), "=r"(r1), "=r"(r2), "=r"(r3) : "r"(addr));
}
__device__ __forceinline__ void mma_f16(float* d, const uint32_t* a, const uint32_t* b) {
    asm volatile(
        "mma.sync.aligned.m16n8k16.row.col.f32.f16.f16.f32 "
        "{%0,%1,%2,%3}, {%4,%5,%6,%7}, {%8,%9}, {%0,%1,%2,%3};"
        : "+f"(d[0]), "+f"(d[1]), "+f"(d[2]), "+f"(d[3])
        : "r"(a[0]), "r"(a[1]), "r"(a[2]), "r"(a[3]), "r"(b[0]), "r"(b[1]));
}
__device__ __forceinline__ uint32_t pk2h(float a, float b) {
    __half2 t = __floats2half2_rn(a, b);
    return *reinterpret_cast<uint32_t*>(&t);
}

// ---------------------------------------------------------------------------
// K0: build tiled+swizzled fp16 A (pos) and B (normalized anchors).
// R12 layout (4096 blocks x 128 threads, thread t -> 8 consecutive cols),
// with the norm reduction done in ONE __syncthreads (each thread sums the
// 4 warp partials itself).
// ---------------------------------------------------------------------------
__global__ __launch_bounds__(128) void prep_kernel(const float* __restrict__ x) {
    const int j = blockIdx.x;
    const int t = threadIdx.x;
    const int by = j >> 7;
    const int r  = j & 127;
    const int c  = t >> 3;            // chunk 0..15
    const int kc = (t & 7) * 8;       // col within chunk

    const float4* px = reinterpret_cast<const float4*>(x + (size_t)j * 2048 + t * 8);
    const float4 p0 = px[0], p1 = px[1];
    const float4* ax = reinterpret_cast<const float4*>(x + (size_t)j * 2048 + 1024 + t * 8);
    const float4 a0 = ax[0], a1 = ax[1];

    float ss = a0.x * a0.x + a0.y * a0.y + a0.z * a0.z + a0.w * a0.w
             + a1.x * a1.x + a1.y * a1.y + a1.z * a1.z + a1.w * a1.w;
    __shared__ float wsum[4];
    #pragma unroll
    for (int o = 16; o > 0; o >>= 1) ss += __shfl_xor_sync(0xffffffffu, ss, o);
    if ((t & 31) == 0) wsum[t >> 5] = ss;
    if (t == 0 && j == 0) { g_count = 0; g_done = 0; }
    __syncthreads();
    const float tot = wsum[0] + wsum[1] + wsum[2] + wsum[3];
    const float rinv = 1.0f / sqrtf(fmaxf(tot, 1e-30f));

    const uint32_t off = SWZ((uint32_t)(r * 128 + kc * 2));
    const size_t tileA = ((size_t)by * NCHUNK + c) * CHUNK_BYTES;

    uint4 v;
    v.x = pk2h(p0.x, p0.y); v.y = pk2h(p0.z, p0.w);
    v.z = pk2h(p1.x, p1.y); v.w = pk2h(p1.z, p1.w);
    *reinterpret_cast<uint4*>(reinterpret_cast<char*>(g_At) + tileA + off) = v;

    v.x = pk2h(a0.x * rinv, a0.y * rinv); v.y = pk2h(a0.z * rinv, a0.w * rinv);
    v.z = pk2h(a1.x * rinv, a1.y * rinv); v.w = pk2h(a1.z * rinv, a1.w * rinv);
    *reinterpret_cast<uint4*>(reinterpret_cast<char*>(g_Bt) + tileA + off) = v;
}

// ---------------------------------------------------------------------------
// K1: persistent fp16 GEMM (R12-proven: static tiles, continuous 3-buffer
// cp.async.bulk pipeline, per-chunk __syncthreads, fused top-2 epilogue).
// ---------------------------------------------------------------------------
__global__ __launch_bounds__(256) void gemm_kernel() {
    extern __shared__ char dyn_smem[];
    char* sm = (char*)((((uintptr_t)dyn_smem) + 1023) & ~(uintptr_t)1023);
    const uint32_t sbase = smem_u32(sm);
    char* epi = sm + NSTAGE * STAGE_BYTES;

    __shared__ __align__(8) uint64_t s_mbar[NSTAGE];

    const int tid = threadIdx.x;
    const int wid = tid >> 5;
    const int lid = tid & 31;
    const int wm = (wid >> 2) * 64;
    const int wn = (wid & 3) * 32;

    uint32_t mb[NSTAGE];
    #pragma unroll
    for (int s = 0; s < NSTAGE; s++) mb[s] = smem_u32(&s_mbar[s]);
    if (tid == 0) {
        #pragma unroll
        for (int s = 0; s < NSTAGE; s++) MBARRIER_INIT(mb[s], 1);
    }
    asm volatile("fence.proxy.async.shared::cta;" ::: "memory");
    __syncthreads();

    const int bid = blockIdx.x;
    int ntiles = 0;
    for (int t = bid; t < NTILES; t += GRIDP) ntiles++;
    if (ntiles == 0) return;
    const int nchunks = ntiles * NCHUNK;

    auto issue_load = [&](int gidx) {
        if (tid == 0) {
            const int tile = bid + (gidx >> 4) * GRIDP;
            const int c = gidx & (NCHUNK - 1);
            const int by = tile >> 5;
            const int bx = tile & 31;
            const int buf = gidx % NSTAGE;
            MBARRIER_EXPECT_TX(mb[buf], STAGE_BYTES);
            bulk_g2s(sbase + buf * STAGE_BYTES,
                     reinterpret_cast<const char*>(g_At) + ((size_t)by * NCHUNK + c) * CHUNK_BYTES,
                     CHUNK_BYTES, mb[buf]);
            bulk_g2s(sbase + buf * STAGE_BYTES + CHUNK_BYTES,
                     reinterpret_cast<const char*>(g_Bt) + ((size_t)bx * NCHUNK + c) * CHUNK_BYTES,
                     CHUNK_BYTES, mb[buf]);
        }
    };

    const int a_row = lid & 15;
    const int a_u   = lid >> 4;
    const int b_row = (lid & 7) + ((lid >> 4) << 3);
    const int b_u   = (lid >> 3) & 1;
    const int quad  = lid & 3;

    float acc[4][4][4];

    auto compute_stage = [&](int buf) {
        const uint32_t stA = sbase + buf * STAGE_BYTES;
        const uint32_t stB = stA + CHUNK_BYTES;
        #pragma unroll
        for (int kk = 0; kk < 4; kk++) {
            uint32_t ah[4][4], bh[4][2];
            #pragma unroll
            for (int mf = 0; mf < 4; mf++) {
                const uint32_t bo = (uint32_t)((wm + mf * 16 + a_row) * 128 + kk * 32 + a_u * 16);
                ldsm_x4(stA + SWZ(bo), ah[mf][0], ah[mf][1], ah[mf][2], ah[mf][3]);
            }
            #pragma unroll
            for (int nf2 = 0; nf2 < 2; nf2++) {
                const uint32_t bo = (uint32_t)((wn + nf2 * 16 + b_row) * 128 + kk * 32 + b_u * 16);
                uint32_t r0, r1, r2, r3;
                ldsm_x4(stB + SWZ(bo), r0, r1, r2, r3);
                bh[nf2 * 2][0] = r0;     bh[nf2 * 2][1] = r1;
                bh[nf2 * 2 + 1][0] = r2; bh[nf2 * 2 + 1][1] = r3;
            }
            #pragma unroll
            for (int mf = 0; mf < 4; mf++)
                #pragma unroll
                for (int nf = 0; nf < 4; nf++)
                    mma_f16(acc[mf][nf], ah[mf], bh[nf]);
        }
    };

    issue_load(0);
    issue_load(1);

    #pragma unroll 1
    for (int g = 0; g < nchunks; ++g) {
        const int c = g & (NCHUNK - 1);
        if (c == 0) {
            #pragma unroll
            for (int m = 0; m < 4; m++)
                #pragma unroll
                for (int n = 0; n < 4; n++)
                    #pragma unroll
                    for (int e = 0; e < 4; e++) acc[m][n][e] = 0.f;
        }
        MBARRIER_WAIT_PARITY(mb[g % NSTAGE], (g / NSTAGE) & 1);
        __syncthreads();   // all warps past chunk g-1 -> buffer (g+2)%3 reusable
        if (g + 2 < nchunks) issue_load(g + 2);
        compute_stage(g % NSTAGE);

        if (c == NCHUNK - 1) {
            // ---------- epilogue (next-tile loads in flight) ----------
            const int tile = bid + (g >> 4) * GRIDP;
            const int by = tile >> 5;
            const int bx = tile & 31;
            const int i0 = by * TMB;
            const int j0 = bx * TNB;

            float* rV1 = (float*)epi;                   // [128][4]
            int*   rI1 = (int*)(epi + 2048);
            float* rV2 = (float*)(epi + 4096);
            int*   rI2 = (int*)(epi + 6144);

            #pragma unroll
            for (int mf = 0; mf < 4; mf++) {
                #pragma unroll
                for (int half = 0; half < 2; half++) {
                    float v1 = -INFINITY, v2 = -INFINITY;
                    int i1 = 0, i2 = 0;
                    #pragma unroll
                    for (int nf = 0; nf < 4; nf++) {
                        #pragma unroll
                        for (int i = 0; i < 2; i++) {
                            const float v = acc[mf][nf][half * 2 + i];
                            const int cc = nf * 8 + quad * 2 + i;
                            if (v > v1) { v2 = v1; i2 = i1; v1 = v; i1 = cc; }
                            else if (v > v2) { v2 = v; i2 = cc; }
                        }
                    }
                    #pragma unroll
                    for (int o = 1; o <= 2; o <<= 1) {
                        const float ov1 = __shfl_xor_sync(0xffffffffu, v1, o);
                        const int   oi1 = __shfl_xor_sync(0xffffffffu, i1, o);
                        const float ov2 = __shfl_xor_sync(0xffffffffu, v2, o);
                        const int   oi2 = __shfl_xor_sync(0xffffffffu, i2, o);
                        if (ov1 > v1 || (ov1 == v1 && oi1 < i1)) {
                            if (v1 > ov2 || (v1 == ov2 && i1 < oi2)) { v2 = v1; i2 = i1; }
                            else { v2 = ov2; i2 = oi2; }
                            v1 = ov1; i1 = oi1;
                        } else {
                            if (ov1 > v2) { v2 = ov1; i2 = oi1; }
                        }
                    }
                    if (quad == 0) {
                        const int row = wm + mf * 16 + (lid >> 2) + half * 8;
                        const int w = wid & 3;
                        rV1[row * 4 + w] = v1; rI1[row * 4 + w] = wn + i1;
                        rV2[row * 4 + w] = v2; rI2[row * 4 + w] = wn + i2;
                    }
                }
            }
            __syncthreads();
            if (tid < 128) {
                float V1 = rV1[tid * 4], V2 = rV2[tid * 4];
                int I1 = rI1[tid * 4], I2 = rI2[tid * 4];
                #pragma unroll
                for (int w = 1; w < 4; w++) {
                    const float v1 = rV1[tid * 4 + w], v2 = rV2[tid * 4 + w];
                    const int i1 = rI1[tid * 4 + w], i2 = rI2[tid * 4 + w];
                    if (v1 > V1) {
                        if (V1 >= v2) { V2 = V1; I2 = I1; } else { V2 = v2; I2 = i2; }
                        V1 = v1; I1 = i1;
                    } else if (v1 > V2) { V2 = v1; I2 = i1; }
                }
                const size_t o = (size_t)(i0 + tid) * NCT + bx;
                g_v1[o] = V1; g_i1[o] = j0 + I1;
                g_v2[o] = V2; g_i2[o] = j0 + I2;
            }
            __syncthreads();   // epi buffer reusable next tile
        }
    }
}

// ---------------------------------------------------------------------------
// K2: warp-per-row merge + exact fp32 rescore + final output (R12-proven).
// ---------------------------------------------------------------------------
__global__ __launch_bounds__(256) void rescore_kernel(const float* __restrict__ x,
                                                      float* __restrict__ out) {
    const int tid = threadIdx.x;
    const int lid = tid & 31;
    const int row = blockIdx.x * 8 + (tid >> 5);

    {
        const size_t o = (size_t)row * NCT + lid;
        float v1 = g_v1[o], v2 = g_v2[o];
        int i1 = g_i1[o], i2 = g_i2[o];
        const float mv1 = v1, mv2 = v2;        // per-tile values for filter
        const int mi1 = i1, mi2 = i2;
        #pragma unroll
        for (int off = 1; off <= 16; off <<= 1) {
            const float ov1 = __shfl_xor_sync(0xffffffffu, v1, off);
            const int   oi1 = __shfl_xor_sync(0xffffffffu, i1, off);
            const float ov2 = __shfl_xor_sync(0xffffffffu, v2, off);
            const int   oi2 = __shfl_xor_sync(0xffffffffu, i2, off);
            if (ov1 > v1 || (ov1 == v1 && oi1 < i1)) {
                if (v1 > ov2 || (v1 == ov2 && i1 < oi2)) { v2 = v1; i2 = i1; }
                else { v2 = ov2; i2 = oi2; }
                v1 = ov1; i1 = oi1;
            } else {
                if (ov1 > v2) { v2 = ov1; i2 = oi1; }
            }
        }
        if ((v1 - v2) >= THR) {
            if (lid == 0 && i1 == row) atomicAdd(&g_count, 1);
        } else {
            // ambiguous: exact fp32 rescore of screen candidates (>= V1 - THR)
            const float cut = v1 - THR;
            unsigned m1 = __ballot_sync(0xffffffffu, mv1 >= cut);
            unsigned m2 = __ballot_sync(0xffffffffu, mv2 >= cut);

            const float4* a4 = reinterpret_cast<const float4*>(x + (size_t)row * 2048 + lid * 32);
            float4 ac[8];
            #pragma unroll
            for (int i = 0; i < 8; i++) ac[i] = a4[i];

            float best = -INFINITY;
            int bi = 1 << 30;
            for (int pass = 0; pass < 2; pass++) {
                unsigned m = pass ? m2 : m1;
                while (m) {
                    const int s = __ffs(m) - 1;
                    m &= m - 1;
                    const int cand = __shfl_sync(0xffffffffu, pass ? mi2 : mi1, s);
                    const float4* b4 = reinterpret_cast<const float4*>(x + (size_t)cand * 2048 + 1024 + lid * 32);
                    float dot = 0.f, nrm = 0.f;
                    #pragma unroll
                    for (int i = 0; i < 8; i++) {
                        const float4 a = ac[i];
                        const float4 b = b4[i];
                        dot = fmaf(a.x, b.x, dot); dot = fmaf(a.y, b.y, dot);
                        dot = fmaf(a.z, b.z, dot); dot = fmaf(a.w, b.w, dot);
                        nrm = fmaf(b.x, b.x, nrm); nrm = fmaf(b.y, b.y, nrm);
                        nrm = fmaf(b.z, b.z, nrm); nrm = fmaf(b.w, b.w, nrm);
                    }
                    #pragma unroll
                    for (int of = 16; of > 0; of >>= 1) {
                        dot += __shfl_xor_sync(0xffffffffu, dot, of);
                        nrm += __shfl_xor_sync(0xffffffffu, nrm, of);
                    }
                    const float val = dot / sqrtf(fmaxf(nrm, 1e-30f));
                    if (val > best || (val == best && cand < bi)) { best = val; bi = cand; }
                }
            }
            if (lid == 0 && bi == row) atomicAdd(&g_count, 1);
        }
    }

    // completion: last block writes the outputs
    __syncthreads();
    if (tid == 0) {
        __threadfence();
        if (atomicAdd(&g_done, 1) == gridDim.x - 1) {
            out[0] = 1.0f;   // nloss == exp(0) exactly
            out[1] = ((float)atomicAdd(&g_count, 0) / 4096.0f) * 100.0f;
        }
    }
}

extern "C" void kernel_launch(void* const* d_in, const int* in_sizes, int n_in,
                              void* d_out, int out_size) {
    const float* x = (const float*)d_in[0];
    float* out = (float*)d_out;

    cudaFuncSetAttribute(gemm_kernel, cudaFuncAttributeMaxDynamicSharedMemorySize, SMEM_BYTES);

    prep_kernel<<<N_ROWS, 128>>>(x);
    gemm_kernel<<<GRIDP, 256, SMEM_BYTES>>>();
    rescore_kernel<<<N_ROWS / 8, 256>>>(x, out);
}